// round 11
// baseline (speedup 1.0000x reference)
#include <cuda_runtime.h>
#include <cuda_bf16.h>

#define NN 1024
#define HH 16
#define DD 64
#define MM 64
#define NB (NN * HH)          // 16384 independent (n,h) pairs

#define GRID_P 912            // 152 SMs x 6 resident CTAs: one persistent wave

static constexpr float MU_C  = 0.9f;
static constexpr float EPS_C = 1e-6f;

// Persistent grid-stride version of the R10 body (128 thr, 16-deep
// front-batched loads, region-grouped .cs store bursts, 6 CTAs/SM).
// grid = 912 = exactly one full wave; each CTA loops b += 912, eliminating
// the ~44%-occupancy tail wave and the ~18 CTA-wave launch/drain transitions.
// Cross-iteration smem reuse is ordered by the two per-iteration barriers.
__global__ __launch_bounds__(128, 6)
void rma_kernel(const float* __restrict__ q_in,
                const float* __restrict__ k_in,
                const float* __restrict__ v_in,
                const float* __restrict__ Si_in,
                const float* __restrict__ Zi_in,
                const float* __restrict__ Pi_in,
                float* __restrict__ Vout,
                float* __restrict__ Sout,
                float* __restrict__ Zout,
                float* __restrict__ Pout)
{
    const int t = threadIdx.x;         // 0..127

    __shared__ float  sQ[DD];
    __shared__ float  sK[DD];
    __shared__ float  sVal[MM];
    __shared__ float  sDotPart[2];
    __shared__ float  sZ;
    __shared__ float4 sAcc[128];

    const int g     = t & 15;          // float4 column group
    const int drow8 = t >> 4;          // 0..7
    const int ob    = drow8 * 16 + g;  // row it adds 128 float4 (2048B)

    for (int b = blockIdx.x; b < NB; b += GRID_P) {

        const int base64   = b * 64;
        const int base4096 = b * 4096;

        const float4* __restrict__ Pi4 = (const float4*)(Pi_in + base4096);
        const float4* __restrict__ Si4 = (const float4*)(Si_in + base4096);

        // ---- 16 front-batched loads (evict-first): Pi burst then Si burst ----
        float4 p0 = __ldcs(Pi4 + ob + 0 * 128);
        float4 p1 = __ldcs(Pi4 + ob + 1 * 128);
        float4 p2 = __ldcs(Pi4 + ob + 2 * 128);
        float4 p3 = __ldcs(Pi4 + ob + 3 * 128);
        float4 p4 = __ldcs(Pi4 + ob + 4 * 128);
        float4 p5 = __ldcs(Pi4 + ob + 5 * 128);
        float4 p6 = __ldcs(Pi4 + ob + 6 * 128);
        float4 p7 = __ldcs(Pi4 + ob + 7 * 128);
        float4 s0 = __ldcs(Si4 + ob + 0 * 128);
        float4 s1 = __ldcs(Si4 + ob + 1 * 128);
        float4 s2 = __ldcs(Si4 + ob + 2 * 128);
        float4 s3 = __ldcs(Si4 + ob + 3 * 128);
        float4 s4 = __ldcs(Si4 + ob + 4 * 128);
        float4 s5 = __ldcs(Si4 + ob + 5 * 128);
        float4 s6 = __ldcs(Si4 + ob + 6 * 128);
        float4 s7 = __ldcs(Si4 + ob + 7 * 128);

        // ---- small vectors: featurize, Zi update, partial dot ----
        if (t < DD) {
            float xq = q_in[base64 + t];
            float fq = (xq > 0.f) ? (xq + 1.f) : __expf(xq);   // elu(x)+1
            sQ[t] = fq;

            float xk = k_in[base64 + t];
            float fk = (xk > 0.f) ? (xk + 1.f) : __expf(xk);
            sK[t] = fk;

            float zn = Zi_in[base64 + t] + fk;
            Zout[base64 + t] = zn;

            float d = fq * zn;
            #pragma unroll
            for (int off = 16; off > 0; off >>= 1)
                d += __shfl_down_sync(0xffffffffu, d, off);
            if ((t & 31) == 0) sDotPart[t >> 5] = d;
        } else {
            sVal[t - 64] = v_in[base64 + (t - 64)];
        }
        __syncthreads();

        if (t == 0) sZ = 1.0f / (sDotPart[0] + sDotPart[1] + EPS_C);
        // (sZ only read after the second __syncthreads)

        const float4 val4 = ((const float4*)sVal)[g];

        float4* __restrict__ Po4 = (float4*)(Pout + base4096);
        float4* __restrict__ So4 = (float4*)(Sout + base4096);

        // ---- phase 1: pn in place over p, Po store burst ----
        #define MK_PN(pp, it)                                           \
        {                                                               \
            const float kk = sK[drow8 + 8 * (it)];                      \
            (pp).x = MU_C * (pp).x - kk * val4.x;                       \
            (pp).y = MU_C * (pp).y - kk * val4.y;                       \
            (pp).z = MU_C * (pp).z - kk * val4.z;                       \
            (pp).w = MU_C * (pp).w - kk * val4.w;                       \
        }
        MK_PN(p0, 0) MK_PN(p1, 1) MK_PN(p2, 2) MK_PN(p3, 3)
        MK_PN(p4, 4) MK_PN(p5, 5) MK_PN(p6, 6) MK_PN(p7, 7)
        #undef MK_PN

        __stcs(Po4 + ob + 0 * 128, p0);
        __stcs(Po4 + ob + 1 * 128, p1);
        __stcs(Po4 + ob + 2 * 128, p2);
        __stcs(Po4 + ob + 3 * 128, p3);
        __stcs(Po4 + ob + 4 * 128, p4);
        __stcs(Po4 + ob + 5 * 128, p5);
        __stcs(Po4 + ob + 6 * 128, p6);
        __stcs(Po4 + ob + 7 * 128, p7);

        // ---- phase 2: sn = s - pn in place over s, So store burst + vacc ----
        float4 vacc = make_float4(0.f, 0.f, 0.f, 0.f);

        #define MK_SN(ss, pp, it)                                       \
        {                                                               \
            const float qq = sQ[drow8 + 8 * (it)];                      \
            (ss).x -= (pp).x;                                           \
            (ss).y -= (pp).y;                                           \
            (ss).z -= (pp).z;                                           \
            (ss).w -= (pp).w;                                           \
            __stcs(So4 + ob + (it) * 128, (ss));                        \
            vacc.x += qq * (ss).x;                                      \
            vacc.y += qq * (ss).y;                                      \
            vacc.z += qq * (ss).z;                                      \
            vacc.w += qq * (ss).w;                                      \
        }
        MK_SN(s0, p0, 0) MK_SN(s1, p1, 1) MK_SN(s2, p2, 2) MK_SN(s3, p3, 3)
        MK_SN(s4, p4, 4) MK_SN(s5, p5, 5) MK_SN(s6, p6, 6) MK_SN(s7, p7, 7)
        #undef MK_SN

        sAcc[t] = vacc;
        __syncthreads();

        // ---- V readout: reduce 8 row-octet partials per m, scale by Z ----
        if (t < MM) {
            const int gg = t >> 2;
            const int c  = t & 3;
            const float* accf = (const float*)sAcc;
            float sum = 0.f;
            #pragma unroll
            for (int r = 0; r < 8; ++r)
                sum += accf[(r * 16 + gg) * 4 + c];
            Vout[base64 + t] = sum * sZ;
        }
        // next iteration's smem writes are ordered after this iteration's
        // reads by barrier1(i+1); sAcc reuse ordered by barrier2(i+1).
    }
}

extern "C" void kernel_launch(void* const* d_in, const int* in_sizes, int n_in,
                              void* d_out, int out_size) {
    // metadata order: query, key, value, Si, Zi, Pi
    const float* q  = (const float*)d_in[0];
    const float* k  = (const float*)d_in[1];
    const float* v  = (const float*)d_in[2];
    const float* Si = (const float*)d_in[3];
    const float* Zi = (const float*)d_in[4];
    const float* Pi = (const float*)d_in[5];

    float* out = (float*)d_out;
    // reference returns (V, Si_new, Zi_new, Pi_new) -> concatenated flat
    float* Vout = out;
    float* Sout = Vout + (size_t)NN * HH * MM;
    float* Zout = Sout + (size_t)NN * HH * DD * MM;
    float* Pout = Zout + (size_t)NN * HH * DD;

    rma_kernel<<<GRID_P, 128>>>(q, k, v, Si, Zi, Pi, Vout, Sout, Zout, Pout);
}

// round 12
// speedup vs baseline: 1.0880x; 1.0880x over previous
#include <cuda_runtime.h>
#include <cuda_bf16.h>

#define NN 1024
#define HH 16
#define DD 64
#define MM 64
#define NB (NN * HH)          // 16384 independent (n,h) pairs

static constexpr float MU_C  = 0.9f;
static constexpr float EPS_C = 1e-6f;

// FINAL (R10): one CTA per (n,h), 128 threads, 16-deep front-batched .cs
// loads (Pi burst then Si burst), region-grouped .cs store bursts, 6 CTAs/SM.
// Measured: 155.6us kernel, DRAM 84.4% (6.69 TB/s) — the memory-controller
// floor for this 1:1 read/write streaming mix; all SM-side restructurings
// (occupancy, pipelining, persistence, barrier elimination, store ordering)
// measured equal or worse across rounds 1-11.
__global__ __launch_bounds__(128, 6)
void rma_kernel(const float* __restrict__ q_in,
                const float* __restrict__ k_in,
                const float* __restrict__ v_in,
                const float* __restrict__ Si_in,
                const float* __restrict__ Zi_in,
                const float* __restrict__ Pi_in,
                float* __restrict__ Vout,
                float* __restrict__ Sout,
                float* __restrict__ Zout,
                float* __restrict__ Pout)
{
    const int b = blockIdx.x;
    const int t = threadIdx.x;         // 0..127

    __shared__ float  sQ[DD];
    __shared__ float  sK[DD];
    __shared__ float  sVal[MM];
    __shared__ float  sDotPart[2];
    __shared__ float  sZ;
    __shared__ float4 sAcc[128];

    const int base64   = b * 64;
    const int base4096 = b * 4096;

    const int g     = t & 15;          // float4 column group
    const int drow8 = t >> 4;          // 0..7

    const float4* __restrict__ Pi4 = (const float4*)(Pi_in + base4096);
    const float4* __restrict__ Si4 = (const float4*)(Si_in + base4096);

    const int ob = drow8 * 16 + g;     // row it adds 128 float4 (2048B)

    // ---- 16 front-batched loads (evict-first): Pi burst then Si burst ----
    float4 p0 = __ldcs(Pi4 + ob + 0 * 128);
    float4 p1 = __ldcs(Pi4 + ob + 1 * 128);
    float4 p2 = __ldcs(Pi4 + ob + 2 * 128);
    float4 p3 = __ldcs(Pi4 + ob + 3 * 128);
    float4 p4 = __ldcs(Pi4 + ob + 4 * 128);
    float4 p5 = __ldcs(Pi4 + ob + 5 * 128);
    float4 p6 = __ldcs(Pi4 + ob + 6 * 128);
    float4 p7 = __ldcs(Pi4 + ob + 7 * 128);
    float4 s0 = __ldcs(Si4 + ob + 0 * 128);
    float4 s1 = __ldcs(Si4 + ob + 1 * 128);
    float4 s2 = __ldcs(Si4 + ob + 2 * 128);
    float4 s3 = __ldcs(Si4 + ob + 3 * 128);
    float4 s4 = __ldcs(Si4 + ob + 4 * 128);
    float4 s5 = __ldcs(Si4 + ob + 5 * 128);
    float4 s6 = __ldcs(Si4 + ob + 6 * 128);
    float4 s7 = __ldcs(Si4 + ob + 7 * 128);

    // ---- small vectors: featurize, Zi update, partial dot (overlaps loads) ----
    if (t < DD) {
        float xq = q_in[base64 + t];
        float fq = (xq > 0.f) ? (xq + 1.f) : __expf(xq);   // elu(x)+1
        sQ[t] = fq;

        float xk = k_in[base64 + t];
        float fk = (xk > 0.f) ? (xk + 1.f) : __expf(xk);
        sK[t] = fk;

        float zn = Zi_in[base64 + t] + fk;
        Zout[base64 + t] = zn;

        float d = fq * zn;
        #pragma unroll
        for (int off = 16; off > 0; off >>= 1)
            d += __shfl_down_sync(0xffffffffu, d, off);
        if ((t & 31) == 0) sDotPart[t >> 5] = d;
    } else {
        sVal[t - 64] = v_in[base64 + (t - 64)];
    }
    __syncthreads();

    if (t == 0) sZ = 1.0f / (sDotPart[0] + sDotPart[1] + EPS_C);
    // (sZ only read after the second __syncthreads)

    const float4 val4 = ((const float4*)sVal)[g];

    float4* __restrict__ Po4 = (float4*)(Pout + base4096);
    float4* __restrict__ So4 = (float4*)(Sout + base4096);

    // ---- phase 1: pn for all rows (in place over p), Po store burst ----
    #define MK_PN(pp, it)                                           \
    {                                                               \
        const float kk = sK[drow8 + 8 * (it)];                      \
        (pp).x = MU_C * (pp).x - kk * val4.x;                       \
        (pp).y = MU_C * (pp).y - kk * val4.y;                       \
        (pp).z = MU_C * (pp).z - kk * val4.z;                       \
        (pp).w = MU_C * (pp).w - kk * val4.w;                       \
    }
    MK_PN(p0, 0) MK_PN(p1, 1) MK_PN(p2, 2) MK_PN(p3, 3)
    MK_PN(p4, 4) MK_PN(p5, 5) MK_PN(p6, 6) MK_PN(p7, 7)
    #undef MK_PN

    __stcs(Po4 + ob + 0 * 128, p0);
    __stcs(Po4 + ob + 1 * 128, p1);
    __stcs(Po4 + ob + 2 * 128, p2);
    __stcs(Po4 + ob + 3 * 128, p3);
    __stcs(Po4 + ob + 4 * 128, p4);
    __stcs(Po4 + ob + 5 * 128, p5);
    __stcs(Po4 + ob + 6 * 128, p6);
    __stcs(Po4 + ob + 7 * 128, p7);

    // ---- phase 2: sn = s - pn (in place over s), So store burst + vacc ----
    float4 vacc = make_float4(0.f, 0.f, 0.f, 0.f);

    #define MK_SN(ss, pp, it)                                       \
    {                                                               \
        const float qq = sQ[drow8 + 8 * (it)];                      \
        (ss).x -= (pp).x;                                           \
        (ss).y -= (pp).y;                                           \
        (ss).z -= (pp).z;                                           \
        (ss).w -= (pp).w;                                           \
        __stcs(So4 + ob + (it) * 128, (ss));                        \
        vacc.x += qq * (ss).x;                                      \
        vacc.y += qq * (ss).y;                                      \
        vacc.z += qq * (ss).z;                                      \
        vacc.w += qq * (ss).w;                                      \
    }
    MK_SN(s0, p0, 0) MK_SN(s1, p1, 1) MK_SN(s2, p2, 2) MK_SN(s3, p3, 3)
    MK_SN(s4, p4, 4) MK_SN(s5, p5, 5) MK_SN(s6, p6, 6) MK_SN(s7, p7, 7)
    #undef MK_SN

    sAcc[t] = vacc;
    __syncthreads();

    // ---- V readout: reduce 8 row-octet partials per m, scale by Z ----
    if (t < MM) {
        const int gg = t >> 2;
        const int c  = t & 3;
        const float* accf = (const float*)sAcc;
        float sum = 0.f;
        #pragma unroll
        for (int r = 0; r < 8; ++r)
            sum += accf[(r * 16 + gg) * 4 + c];
        Vout[base64 + t] = sum * sZ;
    }
}

extern "C" void kernel_launch(void* const* d_in, const int* in_sizes, int n_in,
                              void* d_out, int out_size) {
    // metadata order: query, key, value, Si, Zi, Pi
    const float* q  = (const float*)d_in[0];
    const float* k  = (const float*)d_in[1];
    const float* v  = (const float*)d_in[2];
    const float* Si = (const float*)d_in[3];
    const float* Zi = (const float*)d_in[4];
    const float* Pi = (const float*)d_in[5];

    float* out = (float*)d_out;
    // reference returns (V, Si_new, Zi_new, Pi_new) -> concatenated flat
    float* Vout = out;
    float* Sout = Vout + (size_t)NN * HH * MM;
    float* Zout = Sout + (size_t)NN * HH * DD * MM;
    float* Pout = Zout + (size_t)NN * HH * DD;

    rma_kernel<<<NB, 128>>>(q, k, v, Si, Zi, Pi, Vout, Sout, Zout, Pout);
}

// round 13
// speedup vs baseline: 1.0897x; 1.0016x over previous
#include <cuda_runtime.h>
#include <cuda_bf16.h>

#define NN 1024
#define HH 16
#define DD 64
#define MM 64
#define NB (NN * HH)          // 16384 independent (n,h) pairs

static constexpr float MU_C  = 0.9f;
static constexpr float EPS_C = 1e-6f;

// Few-warps / deep-batch corner: 64 threads per CTA, each thread owns a full
// (n,h) pair column-group across ALL 16 rows it touches: 16 Pi + 16 Si float4
// front-batched (32-deep). Thread t: g = t & 15 (m = 4g..4g+3),
// drow4 = t >> 4 (0..3); rows d = drow4 + 4*it, it = 0..15.
// Lanes 0-15/16-31 of a warp cover adjacent rows -> 512B contiguous per access.
__global__ __launch_bounds__(64, 6)
void rma_kernel(const float* __restrict__ q_in,
                const float* __restrict__ k_in,
                const float* __restrict__ v_in,
                const float* __restrict__ Si_in,
                const float* __restrict__ Zi_in,
                const float* __restrict__ Pi_in,
                float* __restrict__ Vout,
                float* __restrict__ Sout,
                float* __restrict__ Zout,
                float* __restrict__ Pout)
{
    const int b = blockIdx.x;
    const int t = threadIdx.x;         // 0..63

    __shared__ float  sQ[DD];
    __shared__ float  sK[DD];
    __shared__ float  sVal[MM];
    __shared__ float  sDotPart[2];
    __shared__ float  sZ;
    __shared__ float4 sAcc[64];

    const int base64   = b * 64;
    const int base4096 = b * 4096;

    const int g     = t & 15;          // float4 column group
    const int drow4 = t >> 4;          // 0..3

    const float4* __restrict__ Pi4 = (const float4*)(Pi_in + base4096);
    const float4* __restrict__ Si4 = (const float4*)(Si_in + base4096);

    const int ob = drow4 * 16 + g;     // row it adds 4*16 = 64 float4 (1024B)

    // ---- 32 front-batched loads (evict-first): Pi burst then Si burst ----
    float4 p[16], s[16];
    #pragma unroll
    for (int it = 0; it < 16; ++it)
        p[it] = __ldcs(Pi4 + ob + it * 64);
    #pragma unroll
    for (int it = 0; it < 16; ++it)
        s[it] = __ldcs(Si4 + ob + it * 64);

    // ---- small vectors: every thread does element t (overlaps big loads) ----
    {
        float xq = q_in[base64 + t];
        float fq = (xq > 0.f) ? (xq + 1.f) : __expf(xq);   // elu(x)+1
        sQ[t] = fq;

        float xk = k_in[base64 + t];
        float fk = (xk > 0.f) ? (xk + 1.f) : __expf(xk);
        sK[t] = fk;

        float zn = Zi_in[base64 + t] + fk;
        Zout[base64 + t] = zn;

        sVal[t] = v_in[base64 + t];

        float d = fq * zn;
        #pragma unroll
        for (int off = 16; off > 0; off >>= 1)
            d += __shfl_down_sync(0xffffffffu, d, off);
        if ((t & 31) == 0) sDotPart[t >> 5] = d;
    }
    __syncthreads();

    if (t == 0) sZ = 1.0f / (sDotPart[0] + sDotPart[1] + EPS_C);
    // (sZ only read after the second __syncthreads)

    const float4 val4 = ((const float4*)sVal)[g];

    float4* __restrict__ Po4 = (float4*)(Pout + base4096);
    float4* __restrict__ So4 = (float4*)(Sout + base4096);

    // ---- phase 1: pn in place over p, Po store burst ----
    #pragma unroll
    for (int it = 0; it < 16; ++it) {
        const float kk = sK[drow4 + 4 * it];
        p[it].x = MU_C * p[it].x - kk * val4.x;
        p[it].y = MU_C * p[it].y - kk * val4.y;
        p[it].z = MU_C * p[it].z - kk * val4.z;
        p[it].w = MU_C * p[it].w - kk * val4.w;
    }
    #pragma unroll
    for (int it = 0; it < 16; ++it)
        __stcs(Po4 + ob + it * 64, p[it]);

    // ---- phase 2: sn = s - pn in place over s, So store burst + vacc ----
    float4 vacc = make_float4(0.f, 0.f, 0.f, 0.f);
    #pragma unroll
    for (int it = 0; it < 16; ++it) {
        const float qq = sQ[drow4 + 4 * it];
        s[it].x -= p[it].x;
        s[it].y -= p[it].y;
        s[it].z -= p[it].z;
        s[it].w -= p[it].w;
        __stcs(So4 + ob + it * 64, s[it]);
        vacc.x += qq * s[it].x;
        vacc.y += qq * s[it].y;
        vacc.z += qq * s[it].z;
        vacc.w += qq * s[it].w;
    }

    sAcc[t] = vacc;
    __syncthreads();

    // ---- V readout: reduce 4 row-group partials per m, scale by Z ----
    {
        const int gg = t >> 2;
        const int c  = t & 3;
        const float* accf = (const float*)sAcc;
        float sum = 0.f;
        #pragma unroll
        for (int r = 0; r < 4; ++r)
            sum += accf[(r * 16 + gg) * 4 + c];
        Vout[base64 + t] = sum * sZ;
    }
}

extern "C" void kernel_launch(void* const* d_in, const int* in_sizes, int n_in,
                              void* d_out, int out_size) {
    // metadata order: query, key, value, Si, Zi, Pi
    const float* q  = (const float*)d_in[0];
    const float* k  = (const float*)d_in[1];
    const float* v  = (const float*)d_in[2];
    const float* Si = (const float*)d_in[3];
    const float* Zi = (const float*)d_in[4];
    const float* Pi = (const float*)d_in[5];

    float* out = (float*)d_out;
    // reference returns (V, Si_new, Zi_new, Pi_new) -> concatenated flat
    float* Vout = out;
    float* Sout = Vout + (size_t)NN * HH * MM;
    float* Zout = Sout + (size_t)NN * HH * DD * MM;
    float* Pout = Zout + (size_t)NN * HH * DD;

    rma_kernel<<<NB, 64>>>(q, k, v, Si, Zi, Pi, Vout, Sout, Zout, Pout);
}